// round 1
// baseline (speedup 1.0000x reference)
#include <cuda_runtime.h>

#define BB 4
#define TT 2048
#define EE 1024
#define HH 16
#define HD 64

// Scratch (device globals; no allocation allowed in kernel_launch)
__device__ float g_q[BB * HH * TT * HD];   // [B,H,T,HD]
__device__ float g_k[BB * HH * TT * HD];
__device__ float g_v[BB * HH * TT * HD];
__device__ float g_att[BB * TT * EE];      // [B,T,E] (heads concatenated)

// ---------------------------------------------------------------------------
// Kernel A: Q/K/V projections. One block computes a 64(T)x64(HD) tile of
// Q, K and V for one (b,h), sharing the x tile in SMEM.
// ---------------------------------------------------------------------------
__global__ __launch_bounds__(256) void qkv_kernel(
    const float* __restrict__ x,
    const float* __restrict__ Wq,
    const float* __restrict__ Wk,
    const float* __restrict__ Wv)
{
    const int bh = blockIdx.y;
    const int b  = bh / HH;
    const int h  = bh % HH;
    const int t0 = blockIdx.x * 64;

    const int tid = threadIdx.x;
    const int tx  = tid & 15;        // 0..15 (cols)
    const int ty  = tid >> 4;        // 0..15 (rows)

    __shared__ float xs[64][17];
    __shared__ float wqs[16][65];
    __shared__ float wks[16][65];
    __shared__ float wvs[16][65];

    float aq[4][4] = {}, ak[4][4] = {}, av[4][4] = {};

    const float* xb = x  + (size_t)(b * TT + t0) * EE;
    const float* wq = Wq + (size_t)h * EE * HD;
    const float* wk = Wk + (size_t)h * EE * HD;
    const float* wv = Wv + (size_t)h * EE * HD;

    const int lx = tid & 15;         // x-tile col
    const int ly = tid >> 4;         // x-tile row base
    const int wn = tid & 63;         // W-tile col
    const int wk0 = tid >> 6;        // W-tile row base (0..3)

    for (int k0 = 0; k0 < EE; k0 += 16) {
        #pragma unroll
        for (int r = 0; r < 4; r++) {
            xs[ly + 16 * r][lx] = xb[(size_t)(ly + 16 * r) * EE + k0 + lx];
        }
        #pragma unroll
        for (int r = 0; r < 4; r++) {
            int kk = wk0 + 4 * r;
            size_t off = (size_t)(k0 + kk) * HD + wn;
            wqs[kk][wn] = wq[off];
            wks[kk][wn] = wk[off];
            wvs[kk][wn] = wv[off];
        }
        __syncthreads();

        #pragma unroll
        for (int k = 0; k < 16; k++) {
            float a[4];
            #pragma unroll
            for (int i = 0; i < 4; i++) a[i] = xs[ty * 4 + i][k];
            float bq[4], bk_[4], bv[4];
            #pragma unroll
            for (int j = 0; j < 4; j++) {
                bq[j]  = wqs[k][tx * 4 + j];
                bk_[j] = wks[k][tx * 4 + j];
                bv[j]  = wvs[k][tx * 4 + j];
            }
            #pragma unroll
            for (int i = 0; i < 4; i++) {
                #pragma unroll
                for (int j = 0; j < 4; j++) {
                    aq[i][j] = fmaf(a[i], bq[j],  aq[i][j]);
                    ak[i][j] = fmaf(a[i], bk_[j], ak[i][j]);
                    av[i][j] = fmaf(a[i], bv[j],  av[i][j]);
                }
            }
        }
        __syncthreads();
    }

    float* qb = g_q + (size_t)(bh * TT + t0) * HD;
    float* kb = g_k + (size_t)(bh * TT + t0) * HD;
    float* vb = g_v + (size_t)(bh * TT + t0) * HD;
    #pragma unroll
    for (int i = 0; i < 4; i++) {
        int row = ty * 4 + i;
        #pragma unroll
        for (int j = 0; j < 4; j++) {
            int col = tx * 4 + j;
            qb[row * HD + col] = aq[i][j];
            kb[row * HD + col] = ak[i][j];
            vb[row * HD + col] = av[i][j];
        }
    }
}

// ---------------------------------------------------------------------------
// Kernel B: causal flash attention. One block per (b,h, 64-row q tile).
// SMEM: qs[64][65] | ks[64][65] (reused for P) | vs[64][64]  = 49664 B dynamic
// ---------------------------------------------------------------------------
__global__ __launch_bounds__(256) void attn_kernel()
{
    extern __shared__ float smem[];
    float* qs = smem;               // [64][65]
    float* ks = qs + 64 * 65;       // [64][65], reused as P
    float* vs = ks + 64 * 65;       // [64][64]

    const int bh = blockIdx.y;
    const int b  = bh / HH;
    const int h  = bh % HH;
    // reversed so longest blocks (largest q0) launch first
    const int q0 = TT - 64 - blockIdx.x * 64;

    const int tid = threadIdx.x;
    const int tx  = tid & 15;
    const int ty  = tid >> 4;

    const float* qg = g_q + (size_t)(bh * TT + q0) * HD;
    const float* kg = g_k + (size_t)bh * TT * HD;
    const float* vg = g_v + (size_t)bh * TT * HD;

    // Load Q tile, pre-scaled by 1/sqrt(HD) = 0.125
    for (int idx = tid; idx < 64 * 64; idx += 256) {
        int r = idx >> 6, c = idx & 63;
        qs[r * 65 + c] = qg[(size_t)r * HD + c] * 0.125f;
    }

    float m[4], l[4], o[4][4];
    #pragma unroll
    for (int i = 0; i < 4; i++) {
        m[i] = -1e30f; l[i] = 0.f;
        #pragma unroll
        for (int j = 0; j < 4; j++) o[i][j] = 0.f;
    }

    for (int s0 = 0; s0 <= q0; s0 += 64) {
        __syncthreads();
        for (int idx = tid; idx < 64 * 64; idx += 256) {
            int r = idx >> 6, c = idx & 63;
            ks[r * 65 + c] = kg[(size_t)(s0 + r) * HD + c];
            vs[r * 64 + c] = vg[(size_t)(s0 + r) * HD + c];
        }
        __syncthreads();

        // S = Q K^T  (64x64x64)
        float s[4][4] = {};
        #pragma unroll
        for (int k = 0; k < 64; k++) {
            float a[4], bb[4];
            #pragma unroll
            for (int i = 0; i < 4; i++) a[i]  = qs[(ty * 4 + i) * 65 + k];
            #pragma unroll
            for (int j = 0; j < 4; j++) bb[j] = ks[(tx * 4 + j) * 65 + k];
            #pragma unroll
            for (int i = 0; i < 4; i++)
                #pragma unroll
                for (int j = 0; j < 4; j++)
                    s[i][j] = fmaf(a[i], bb[j], s[i][j]);
        }

        // causal mask (only the diagonal tile needs it)
        if (s0 == q0) {
            #pragma unroll
            for (int i = 0; i < 4; i++)
                #pragma unroll
                for (int j = 0; j < 4; j++)
                    if (tx * 4 + j > ty * 4 + i) s[i][j] = -1e30f;
        }

        // row max across the 16 tx-threads of this row group
        float rm[4];
        #pragma unroll
        for (int i = 0; i < 4; i++) {
            rm[i] = fmaxf(fmaxf(s[i][0], s[i][1]), fmaxf(s[i][2], s[i][3]));
        }
        #pragma unroll
        for (int off = 1; off < 16; off <<= 1) {
            #pragma unroll
            for (int i = 0; i < 4; i++)
                rm[i] = fmaxf(rm[i], __shfl_xor_sync(0xffffffffu, rm[i], off));
        }

        float mn[4], fac[4], rs[4];
        #pragma unroll
        for (int i = 0; i < 4; i++) {
            mn[i]  = fmaxf(m[i], rm[i]);
            fac[i] = __expf(m[i] - mn[i]);
            rs[i]  = 0.f;
        }
        #pragma unroll
        for (int i = 0; i < 4; i++) {
            #pragma unroll
            for (int j = 0; j < 4; j++) {
                s[i][j] = __expf(s[i][j] - mn[i]);
                rs[i] += s[i][j];
            }
        }
        #pragma unroll
        for (int off = 1; off < 16; off <<= 1) {
            #pragma unroll
            for (int i = 0; i < 4; i++)
                rs[i] += __shfl_xor_sync(0xffffffffu, rs[i], off);
        }
        #pragma unroll
        for (int i = 0; i < 4; i++) {
            l[i] = l[i] * fac[i] + rs[i];
            m[i] = mn[i];
            #pragma unroll
            for (int j = 0; j < 4; j++) o[i][j] *= fac[i];
        }

        // write P into ks buffer, then O += P @ V
        __syncthreads();
        #pragma unroll
        for (int i = 0; i < 4; i++)
            #pragma unroll
            for (int j = 0; j < 4; j++)
                ks[(ty * 4 + i) * 65 + tx * 4 + j] = s[i][j];
        __syncthreads();

        #pragma unroll
        for (int k = 0; k < 64; k++) {
            float a[4], bb[4];
            #pragma unroll
            for (int i = 0; i < 4; i++) a[i]  = ks[(ty * 4 + i) * 65 + k];
            #pragma unroll
            for (int j = 0; j < 4; j++) bb[j] = vs[k * 64 + tx * 4 + j];
            #pragma unroll
            for (int i = 0; i < 4; i++)
                #pragma unroll
                for (int j = 0; j < 4; j++)
                    o[i][j] = fmaf(a[i], bb[j], o[i][j]);
        }
    }

    // epilogue: normalize, write [B,T,E] with head offset
    float* og = g_att + (size_t)(b * TT + q0) * EE + h * HD;
    #pragma unroll
    for (int i = 0; i < 4; i++) {
        float inv = 1.0f / l[i];
        #pragma unroll
        for (int j = 0; j < 4; j++)
            og[(size_t)(ty * 4 + i) * EE + tx * 4 + j] = o[i][j] * inv;
    }
}

// ---------------------------------------------------------------------------
// Kernel C: out = att @ Wo^T + bo.   [8192,1024] x [1024,1024]^T
// ---------------------------------------------------------------------------
__global__ __launch_bounds__(256) void oproj_kernel(
    const float* __restrict__ Wo,
    const float* __restrict__ bo,
    float* __restrict__ out)
{
    const int n0 = blockIdx.x * 64;
    const int m0 = blockIdx.y * 64;

    const int tid = threadIdx.x;
    const int tx  = tid & 15;
    const int ty  = tid >> 4;

    __shared__ float as[64][17];
    __shared__ float bs[16][65];

    float acc[4][4] = {};

    const int alx = tid & 15;       // A col
    const int aly = tid >> 4;       // A row base
    const int bk  = tid & 15;       // B k (contiguous in Wo row)
    const int bn  = tid >> 4;       // B n base

    for (int k0 = 0; k0 < EE; k0 += 16) {
        #pragma unroll
        for (int r = 0; r < 4; r++) {
            as[aly + 16 * r][alx] =
                g_att[(size_t)(m0 + aly + 16 * r) * EE + k0 + alx];
        }
        #pragma unroll
        for (int r = 0; r < 4; r++) {
            int n = bn + 16 * r;
            bs[bk][n] = Wo[(size_t)(n0 + n) * EE + k0 + bk];
        }
        __syncthreads();

        #pragma unroll
        for (int k = 0; k < 16; k++) {
            float a[4], bb[4];
            #pragma unroll
            for (int i = 0; i < 4; i++) a[i]  = as[ty * 4 + i][k];
            #pragma unroll
            for (int j = 0; j < 4; j++) bb[j] = bs[k][tx * 4 + j];
            #pragma unroll
            for (int i = 0; i < 4; i++)
                #pragma unroll
                for (int j = 0; j < 4; j++)
                    acc[i][j] = fmaf(a[i], bb[j], acc[i][j]);
        }
        __syncthreads();
    }

    #pragma unroll
    for (int i = 0; i < 4; i++) {
        #pragma unroll
        for (int j = 0; j < 4; j++) {
            int n = n0 + tx * 4 + j;
            out[(size_t)(m0 + ty * 4 + i) * EE + n] = acc[i][j] + bo[n];
        }
    }
}

// ---------------------------------------------------------------------------
extern "C" void kernel_launch(void* const* d_in, const int* in_sizes, int n_in,
                              void* d_out, int out_size)
{
    const float* x  = (const float*)d_in[0];
    const float* Wq = (const float*)d_in[1];
    const float* Wk = (const float*)d_in[2];
    const float* Wv = (const float*)d_in[3];
    const float* Wo = (const float*)d_in[4];
    const float* bo = (const float*)d_in[5];
    float* out = (float*)d_out;

    dim3 gridA(TT / 64, BB * HH);
    qkv_kernel<<<gridA, 256>>>(x, Wq, Wk, Wv);

    const size_t smemB = (size_t)(64 * 65 + 64 * 65 + 64 * 64) * sizeof(float); // 49664
    cudaFuncSetAttribute(attn_kernel,
                         cudaFuncAttributeMaxDynamicSharedMemorySize,
                         (int)smemB);
    dim3 gridB(TT / 64, BB * HH);
    attn_kernel<<<gridB, 256, smemB>>>();

    dim3 gridC(EE / 64, (BB * TT) / 64);
    oproj_kernel<<<gridC, 256>>>(Wo, bo, out);
}

// round 4
// speedup vs baseline: 3.5405x; 3.5405x over previous
#include <cuda_runtime.h>
#include <cstdint>

#define BB 4
#define TT 2048
#define EE 1024
#define HH 16
#define HD 64

// ---------------------------------------------------------------------------
// Scratch (device globals; no allocation allowed anywhere). 16B-aligned for
// float4 / cp.async access.
// ---------------------------------------------------------------------------
__device__ __align__(16) float g_q[BB * HH * TT * HD];   // [B,H,T,HD]
__device__ __align__(16) float g_k[BB * HH * TT * HD];
__device__ __align__(16) float g_v[BB * HH * TT * HD];
__device__ __align__(16) float g_att[BB * TT * EE];      // [B,T,E]
__device__ __align__(16) float g_wt[3 * EE * EE];        // K-major weights [3072][1024]

// ---------------------------------------------------------------------------
// Helpers
// ---------------------------------------------------------------------------
__device__ __forceinline__ uint32_t smem_u32(const void* p) {
    uint32_t a;
    asm("{ .reg .u64 t; cvta.to.shared.u64 t, %1; cvt.u32.u64 %0, t; }"
        : "=r"(a) : "l"(p));
    return a;
}

// round-to-nearest tf32 bits of an f32
__device__ __forceinline__ uint32_t t32(float x) {
    uint32_t u;
    asm("cvt.rna.tf32.f32 %0, %1;" : "=r"(u) : "f"(x));
    return u;
}
__device__ __forceinline__ float tf32f(float x) { return __uint_as_float(t32(x)); }

// m16n8k8 tf32 MMA, C/D in f32 (sm_80+ portable path; tcgen05 is rejected by
// this harness's compute_103 PTX stage)
__device__ __forceinline__ void mma8(float c[4],
                                     uint32_t a0, uint32_t a1, uint32_t a2, uint32_t a3,
                                     uint32_t b0, uint32_t b1) {
    asm volatile(
        "mma.sync.aligned.m16n8k8.row.col.f32.tf32.tf32.f32 "
        "{%0,%1,%2,%3},{%4,%5,%6,%7},{%8,%9},{%0,%1,%2,%3};"
        : "+f"(c[0]), "+f"(c[1]), "+f"(c[2]), "+f"(c[3])
        : "r"(a0), "r"(a1), "r"(a2), "r"(a3), "r"(b0), "r"(b1));
}

#define CP16(dst, src) \
    asm volatile("cp.async.cg.shared.global [%0], [%1], 16;" :: "r"(dst), "l"(src))
#define CP_COMMIT()  asm volatile("cp.async.commit_group;" ::: "memory")
#define CP_WAIT1()   asm volatile("cp.async.wait_group 1;" ::: "memory")
#define CP_WAIT0()   asm volatile("cp.async.wait_group 0;" ::: "memory")

// ---------------------------------------------------------------------------
// Weight transpose: g_wt[n][k] = W_m[h][k][d],  n = m*1024 + h*64 + d
// ---------------------------------------------------------------------------
__global__ __launch_bounds__(256) void wt_transpose_kernel(
    const float* __restrict__ Wq,
    const float* __restrict__ Wk,
    const float* __restrict__ Wv)
{
    const float* Ws[3] = {Wq, Wk, Wv};
    const int m  = blockIdx.z;
    const int h  = blockIdx.y >> 1;
    const int d0 = (blockIdx.y & 1) * 32;
    const int k0 = blockIdx.x * 32;

    __shared__ float tile[32][33];
    const int tx = threadIdx.x;   // 0..31
    const int ty = threadIdx.y;   // 0..7

    const float* src = Ws[m] + (size_t)h * EE * HD;
    #pragma unroll
    for (int i = 0; i < 4; i++)
        tile[ty + 8 * i][tx] = src[(size_t)(k0 + ty + 8 * i) * HD + d0 + tx];
    __syncthreads();

    #pragma unroll
    for (int i = 0; i < 4; i++) {
        int n = m * 1024 + h * 64 + d0 + ty + 8 * i;
        g_wt[(size_t)n * EE + k0 + tx] = tile[tx][ty + 8 * i];
    }
}

// ---------------------------------------------------------------------------
// tf32 mma.sync GEMM:  C[M,N] = A[M,K] @ B[N,K]^T
// Block tile 128x128, K-chunk 32 (stride 36 => conflict-free fragment loads),
// cp.async double buffered.
// mode 0: QKV  (A=x [8192,1024], B=g_wt [3072,1024], scatter -> g_q/g_k/g_v)
// mode 1: OPROJ(A=g_att,         B=Wo   [1024,1024], out = C + bo)
// ---------------------------------------------------------------------------
__global__ __launch_bounds__(256, 1) void gemm_tf32_kernel(
    int mode,
    const float* __restrict__ A,
    const float* __restrict__ Bsrc,
    const float* __restrict__ bias,
    float* __restrict__ out)
{
    extern __shared__ float sm[];
    float* Asm = sm;                 // [2][128*36]
    float* Bsm = sm + 2 * 4608;      // [2][128*36]

    const int tid  = threadIdx.x;
    const int lane = tid & 31;
    const int wid  = tid >> 5;
    const int wm   = (wid >> 2) * 64;     // warp M offset (0 or 64)
    const int wn   = (wid & 3) * 32;      // warp N offset (0,32,64,96)
    const int r    = lane >> 2;           // 0..7
    const int qd   = lane & 3;            // 0..3

    const int m0 = blockIdx.y * 128;
    const int n0 = blockIdx.x * 128;

    float c[4][4][4] = {};

    auto issue = [&](int cidx) {
        const int p  = cidx & 1;
        const int k0 = cidx * 32;
        #pragma unroll
        for (int rr = 0; rr < 4; rr++) {
            int it  = tid + 256 * rr;
            int row = it >> 3;
            int f4  = it & 7;
            uint32_t da = smem_u32(Asm + p * 4608 + row * 36 + f4 * 4);
            CP16(da, A + (size_t)(m0 + row) * EE + k0 + f4 * 4);
            uint32_t db = smem_u32(Bsm + p * 4608 + row * 36 + f4 * 4);
            CP16(db, Bsrc + (size_t)(n0 + row) * EE + k0 + f4 * 4);
        }
        CP_COMMIT();
    };

    issue(0);
    for (int cc = 0; cc < 32; cc++) {
        const int p = cc & 1;
        if (cc + 1 < 32) { issue(cc + 1); CP_WAIT1(); }
        else             { CP_WAIT0(); }
        __syncthreads();

        const float* ap = Asm + p * 4608;
        const float* bp = Bsm + p * 4608;
        #pragma unroll
        for (int k8 = 0; k8 < 4; k8++) {
            const int kk = k8 * 8;
            uint32_t a[4][4];
            #pragma unroll
            for (int i = 0; i < 4; i++) {
                a[i][0] = t32(ap[(wm + i * 16 + r)     * 36 + kk + qd]);
                a[i][1] = t32(ap[(wm + i * 16 + r + 8) * 36 + kk + qd]);
                a[i][2] = t32(ap[(wm + i * 16 + r)     * 36 + kk + qd + 4]);
                a[i][3] = t32(ap[(wm + i * 16 + r + 8) * 36 + kk + qd + 4]);
            }
            #pragma unroll
            for (int j = 0; j < 4; j++) {
                uint32_t b0 = t32(bp[(wn + j * 8 + r) * 36 + kk + qd]);
                uint32_t b1 = t32(bp[(wn + j * 8 + r) * 36 + kk + qd + 4]);
                #pragma unroll
                for (int i = 0; i < 4; i++)
                    mma8(c[i][j], a[i][0], a[i][1], a[i][2], a[i][3], b0, b1);
            }
        }
        __syncthreads();
    }

    // ---- epilogue ----
    #pragma unroll
    for (int i = 0; i < 4; i++) {
        const int gm0 = m0 + wm + i * 16 + r;     // rows for c0/c1; +8 for c2/c3
        if (mode == 0) {
            const int b = gm0 >> 11;
            const int t = gm0 & 2047;
            #pragma unroll
            for (int j = 0; j < 4; j++) {
                const int col = n0 + wn + j * 8 + qd * 2;
                const int mat = col >> 10;
                const int rem = col & 1023;
                const int h   = rem >> 6;
                const int d   = rem & 63;
                float* base = (mat == 0) ? g_q : (mat == 1 ? g_k : g_v);
                size_t o0 = ((size_t)((b * 16 + h) * 2048 + t)) * 64 + d;
                *(float2*)(base + o0)          = make_float2(c[i][j][0], c[i][j][1]);
                *(float2*)(base + o0 + 8 * 64) = make_float2(c[i][j][2], c[i][j][3]);
            }
        } else {
            #pragma unroll
            for (int j = 0; j < 4; j++) {
                const int col = n0 + wn + j * 8 + qd * 2;
                float2 bv = *(const float2*)(bias + col);
                float* d0 = out + (size_t)gm0 * EE + col;
                *(float2*)d0            = make_float2(c[i][j][0] + bv.x, c[i][j][1] + bv.y);
                *(float2*)(d0 + 8 * EE) = make_float2(c[i][j][2] + bv.x, c[i][j][3] + bv.y);
            }
        }
    }
}

// ---------------------------------------------------------------------------
// Causal flash attention with tf32 mma.sync.
// Block = 128 threads (4 warps); each warp owns 16 q-rows x 64 cols.
// Dynamic SMEM: Qs/Ks/Ps stride 68 (conflict-free: bank = lane), Vs stride 72.
// ---------------------------------------------------------------------------
#define QS  (64 * 68)
#define VSZ (64 * 72)

__global__ __launch_bounds__(128) void attn_kernel()
{
    extern __shared__ float asm_[];
    float* Qs = asm_;              // [64][68]
    float* Ks = Qs + QS;           // [64][68]
    float* Ps = Ks + QS;           // [64][68]
    float* Vs = Ps + QS;           // [64][72]

    const int bh = blockIdx.y;
    const int b  = bh >> 4;
    const int h  = bh & 15;
    const int q0 = TT - 64 - blockIdx.x * 64;   // longest tiles first

    const int tid  = threadIdx.x;
    const int lane = tid & 31;
    const int wid  = tid >> 5;
    const int wm   = wid * 16;      // warp's 16-row slice
    const int r    = lane >> 2;     // 0..7
    const int qd   = lane & 3;      // 0..3

    const float* qg = g_q + ((size_t)bh * TT + q0) * HD;
    const float* kg = g_k + (size_t)bh * TT * HD;
    const float* vg = g_v + (size_t)bh * TT * HD;

    // load Q (scale by 1/8, round to tf32)
    for (int it = tid; it < 1024; it += 128) {
        int row = it >> 4, f4 = it & 15;
        float4 v = *(const float4*)(qg + row * 64 + f4 * 4);
        float4 w = make_float4(tf32f(v.x * 0.125f), tf32f(v.y * 0.125f),
                               tf32f(v.z * 0.125f), tf32f(v.w * 0.125f));
        *(float4*)(Qs + row * 68 + f4 * 4) = w;
    }

    float o[8][4] = {};
    float m0r = -1e30f, m1r = -1e30f, l0 = 0.f, l1 = 0.f;

    for (int s0 = 0; s0 <= q0; s0 += 64) {
        __syncthreads();
        for (int it = tid; it < 1024; it += 128) {
            int row = it >> 4, f4 = it & 15;
            float4 kv = *(const float4*)(kg + (size_t)(s0 + row) * 64 + f4 * 4);
            *(float4*)(Ks + row * 68 + f4 * 4) =
                make_float4(tf32f(kv.x), tf32f(kv.y), tf32f(kv.z), tf32f(kv.w));
            float4 vv = *(const float4*)(vg + (size_t)(s0 + row) * 64 + f4 * 4);
            *(float4*)(Vs + row * 72 + f4 * 4) =
                make_float4(tf32f(vv.x), tf32f(vv.y), tf32f(vv.z), tf32f(vv.w));
        }
        __syncthreads();

        // ---- S = Q K^T (16 x 64 per warp) ----
        float c[8][4] = {};
        #pragma unroll
        for (int k8 = 0; k8 < 8; k8++) {
            const int kk = k8 * 8;
            uint32_t a0 = __float_as_uint(Qs[(wm + r)     * 68 + kk + qd]);
            uint32_t a1 = __float_as_uint(Qs[(wm + r + 8) * 68 + kk + qd]);
            uint32_t a2 = __float_as_uint(Qs[(wm + r)     * 68 + kk + qd + 4]);
            uint32_t a3 = __float_as_uint(Qs[(wm + r + 8) * 68 + kk + qd + 4]);
            #pragma unroll
            for (int j = 0; j < 8; j++) {
                uint32_t b0 = __float_as_uint(Ks[(j * 8 + r) * 68 + kk + qd]);
                uint32_t b1 = __float_as_uint(Ks[(j * 8 + r) * 68 + kk + qd + 4]);
                mma8(c[j], a0, a1, a2, a3, b0, b1);
            }
        }

        // ---- causal mask (diagonal tile only) ----
        if (s0 == q0) {
            const int row0 = wm + r, row1 = row0 + 8;
            #pragma unroll
            for (int j = 0; j < 8; j++) {
                const int cl = j * 8 + qd * 2;
                if (cl     > row0) c[j][0] = -1e30f;
                if (cl + 1 > row0) c[j][1] = -1e30f;
                if (cl     > row1) c[j][2] = -1e30f;
                if (cl + 1 > row1) c[j][3] = -1e30f;
            }
        }

        // ---- online softmax on fragments (rows live inside one quad) ----
        float mx0 = -1e30f, mx1 = -1e30f;
        #pragma unroll
        for (int j = 0; j < 8; j++) {
            mx0 = fmaxf(mx0, fmaxf(c[j][0], c[j][1]));
            mx1 = fmaxf(mx1, fmaxf(c[j][2], c[j][3]));
        }
        mx0 = fmaxf(mx0, __shfl_xor_sync(0xffffffffu, mx0, 1));
        mx0 = fmaxf(mx0, __shfl_xor_sync(0xffffffffu, mx0, 2));
        mx1 = fmaxf(mx1, __shfl_xor_sync(0xffffffffu, mx1, 1));
        mx1 = fmaxf(mx1, __shfl_xor_sync(0xffffffffu, mx1, 2));

        const float nm0 = fmaxf(m0r, mx0), nm1 = fmaxf(m1r, mx1);
        const float f0 = __expf(m0r - nm0), f1 = __expf(m1r - nm1);
        float rs0 = 0.f, rs1 = 0.f;
        #pragma unroll
        for (int j = 0; j < 8; j++) {
            c[j][0] = __expf(c[j][0] - nm0);
            c[j][1] = __expf(c[j][1] - nm0);
            c[j][2] = __expf(c[j][2] - nm1);
            c[j][3] = __expf(c[j][3] - nm1);
            rs0 += c[j][0] + c[j][1];
            rs1 += c[j][2] + c[j][3];
        }
        rs0 += __shfl_xor_sync(0xffffffffu, rs0, 1);
        rs0 += __shfl_xor_sync(0xffffffffu, rs0, 2);
        rs1 += __shfl_xor_sync(0xffffffffu, rs1, 1);
        rs1 += __shfl_xor_sync(0xffffffffu, rs1, 2);

        l0 = l0 * f0 + rs0;  m0r = nm0;
        l1 = l1 * f1 + rs1;  m1r = nm1;
        #pragma unroll
        for (int j = 0; j < 8; j++) {
            o[j][0] *= f0;  o[j][1] *= f0;
            o[j][2] *= f1;  o[j][3] *= f1;
        }

        // ---- P -> warp-private SMEM rows (tf32-rounded), then O += P V ----
        #pragma unroll
        for (int j = 0; j < 8; j++) {
            *(float2*)(Ps + (wm + r)     * 68 + j * 8 + qd * 2) =
                make_float2(tf32f(c[j][0]), tf32f(c[j][1]));
            *(float2*)(Ps + (wm + r + 8) * 68 + j * 8 + qd * 2) =
                make_float2(tf32f(c[j][2]), tf32f(c[j][3]));
        }
        __syncwarp();

        #pragma unroll
        for (int k8 = 0; k8 < 8; k8++) {
            const int kk = k8 * 8;
            uint32_t a0 = __float_as_uint(Ps[(wm + r)     * 68 + kk + qd]);
            uint32_t a1 = __float_as_uint(Ps[(wm + r + 8) * 68 + kk + qd]);
            uint32_t a2 = __float_as_uint(Ps[(wm + r)     * 68 + kk + qd + 4]);
            uint32_t a3 = __float_as_uint(Ps[(wm + r + 8) * 68 + kk + qd + 4]);
            #pragma unroll
            for (int j = 0; j < 8; j++) {
                uint32_t b0 = __float_as_uint(Vs[(kk + qd)     * 72 + j * 8 + r]);
                uint32_t b1 = __float_as_uint(Vs[(kk + qd + 4) * 72 + j * 8 + r]);
                mma8(o[j], a0, a1, a2, a3, b0, b1);
            }
        }
    }

    // ---- epilogue: normalize, write to g_att[B,T,E] ----
    const float inv0 = 1.0f / l0, inv1 = 1.0f / l1;
    const int t0 = q0 + wm + r;
    float* og0 = g_att + ((size_t)b * TT + t0) * EE + h * 64;
    float* og1 = og0 + 8 * EE;
    #pragma unroll
    for (int j = 0; j < 8; j++) {
        *(float2*)(og0 + j * 8 + qd * 2) = make_float2(o[j][0] * inv0, o[j][1] * inv0);
        *(float2*)(og1 + j * 8 + qd * 2) = make_float2(o[j][2] * inv1, o[j][3] * inv1);
    }
}

// ---------------------------------------------------------------------------
extern "C" void kernel_launch(void* const* d_in, const int* in_sizes, int n_in,
                              void* d_out, int out_size)
{
    const float* x  = (const float*)d_in[0];
    const float* Wq = (const float*)d_in[1];
    const float* Wk = (const float*)d_in[2];
    const float* Wv = (const float*)d_in[3];
    const float* Wo = (const float*)d_in[4];
    const float* bo = (const float*)d_in[5];
    float* out = (float*)d_out;

    // 1) pack per-head weights K-major
    {
        dim3 grid(EE / 32, HH * 2, 3);
        dim3 blk(32, 8);
        wt_transpose_kernel<<<grid, blk>>>(Wq, Wk, Wv);
    }

    const int gemm_smem = 4 * 4608 * sizeof(float);           // 73728 B
    cudaFuncSetAttribute(gemm_tf32_kernel,
                         cudaFuncAttributeMaxDynamicSharedMemorySize, gemm_smem);
    const int attn_smem = (3 * QS + VSZ) * sizeof(float);     // 70656 B
    cudaFuncSetAttribute(attn_kernel,
                         cudaFuncAttributeMaxDynamicSharedMemorySize, attn_smem);

    float* wt_ptr = nullptr;
    cudaGetSymbolAddress((void**)&wt_ptr, g_wt);
    float* att_ptr = nullptr;
    cudaGetSymbolAddress((void**)&att_ptr, g_att);

    // 2) QKV: C[8192,3072] = x @ g_wt^T  (scattered into g_q/g_k/g_v)
    {
        dim3 grid(3 * EE / 128, (BB * TT) / 128);   // (24, 64)
        gemm_tf32_kernel<<<grid, 256, gemm_smem>>>(0, x, wt_ptr, nullptr, nullptr);
    }

    // 3) attention
    {
        dim3 gridB(TT / 64, BB * HH);
        attn_kernel<<<gridB, 128, attn_smem>>>();
    }

    // 4) O projection: out = g_att @ Wo^T + bo
    {
        dim3 grid(EE / 128, (BB * TT) / 128);       // (8, 64)
        gemm_tf32_kernel<<<grid, 256, gemm_smem>>>(1, att_ptr, Wo, bo, out);
    }
}

// round 5
// speedup vs baseline: 3.5582x; 1.0050x over previous
#include <cuda_runtime.h>
#include <cstdint>

#define BB 4
#define TT 2048
#define EE 1024
#define HH 16
#define HD 64

// ---------------------------------------------------------------------------
// Scratch (device globals; no allocation allowed anywhere). 16B-aligned.
// ---------------------------------------------------------------------------
__device__ __align__(16) float g_q[BB * HH * TT * HD];   // [B,H,T,HD] (tf32-rounded)
__device__ __align__(16) float g_k[BB * HH * TT * HD];
__device__ __align__(16) float g_v[BB * HH * TT * HD];
__device__ __align__(16) float g_att[BB * TT * EE];      // [B,T,E]   (tf32-rounded)
__device__ __align__(16) float g_wt[3 * EE * EE];        // K-major weights (rounded)
__device__ __align__(16) float g_xr[BB * TT * EE];       // rounded x
__device__ __align__(16) float g_wo[EE * EE];            // rounded Wo

// ---------------------------------------------------------------------------
// Helpers
// ---------------------------------------------------------------------------
__device__ __forceinline__ uint32_t smem_u32(const void* p) {
    uint32_t a;
    asm("{ .reg .u64 t; cvta.to.shared.u64 t, %1; cvt.u32.u64 %0, t; }"
        : "=r"(a) : "l"(p));
    return a;
}

__device__ __forceinline__ uint32_t t32(float x) {
    uint32_t u;
    asm("cvt.rna.tf32.f32 %0, %1;" : "=r"(u) : "f"(x));
    return u;
}
__device__ __forceinline__ float tf32f(float x) { return __uint_as_float(t32(x)); }

__device__ __forceinline__ void mma8(float c[4],
                                     uint32_t a0, uint32_t a1, uint32_t a2, uint32_t a3,
                                     uint32_t b0, uint32_t b1) {
    asm volatile(
        "mma.sync.aligned.m16n8k8.row.col.f32.tf32.tf32.f32 "
        "{%0,%1,%2,%3},{%4,%5,%6,%7},{%8,%9},{%0,%1,%2,%3};"
        : "+f"(c[0]), "+f"(c[1]), "+f"(c[2]), "+f"(c[3])
        : "r"(a0), "r"(a1), "r"(a2), "r"(a3), "r"(b0), "r"(b1));
}

#define CP16(dst, src) \
    asm volatile("cp.async.cg.shared.global [%0], [%1], 16;" :: "r"(dst), "l"(src))
#define CP_COMMIT()  asm volatile("cp.async.commit_group;" ::: "memory")
#define CP_WAIT1()   asm volatile("cp.async.wait_group 1;" ::: "memory")
#define CP_WAIT0()   asm volatile("cp.async.wait_group 0;" ::: "memory")

// ---------------------------------------------------------------------------
// tf32 pre-rounding pass (vectorized). n4 = element count / 4.
// ---------------------------------------------------------------------------
__global__ __launch_bounds__(256) void round_kernel(const float4* __restrict__ src,
                                                    float4* __restrict__ dst, int n4)
{
    int i = blockIdx.x * 256 + threadIdx.x;
    if (i < n4) {
        float4 v = src[i];
        dst[i] = make_float4(tf32f(v.x), tf32f(v.y), tf32f(v.z), tf32f(v.w));
    }
}

// ---------------------------------------------------------------------------
// Weight transpose + round: g_wt[n][k] = round(W_m[h][k][d]), n = m*1024+h*64+d
// ---------------------------------------------------------------------------
__global__ __launch_bounds__(256) void wt_transpose_kernel(
    const float* __restrict__ Wq,
    const float* __restrict__ Wk,
    const float* __restrict__ Wv)
{
    const float* Ws[3] = {Wq, Wk, Wv};
    const int m  = blockIdx.z;
    const int h  = blockIdx.y >> 1;
    const int d0 = (blockIdx.y & 1) * 32;
    const int k0 = blockIdx.x * 32;

    __shared__ float tile[32][33];
    const int tx = threadIdx.x;   // 0..31
    const int ty = threadIdx.y;   // 0..7

    const float* src = Ws[m] + (size_t)h * EE * HD;
    #pragma unroll
    for (int i = 0; i < 4; i++)
        tile[ty + 8 * i][tx] = src[(size_t)(k0 + ty + 8 * i) * HD + d0 + tx];
    __syncthreads();

    #pragma unroll
    for (int i = 0; i < 4; i++) {
        int n = m * 1024 + h * 64 + d0 + ty + 8 * i;
        g_wt[(size_t)n * EE + k0 + tx] = tf32f(tile[tx][ty + 8 * i]);
    }
}

// ---------------------------------------------------------------------------
// tf32 mma.sync GEMM:  C[M,N] = A[M,K] @ B[N,K]^T.  Inputs pre-rounded to tf32
// so the inner loop does raw LDS (MMA truncation is exact).
// Block tile 128x128, K-chunk 32 (stride 36 => conflict-free), cp.async x2.
// mode 0: QKV  (A=g_xr, B=g_wt, scatter rounded -> g_q/g_k/g_v)
// mode 1: OPROJ(A=g_att, B=g_wo, out = C + bo)
// ---------------------------------------------------------------------------
__global__ __launch_bounds__(256, 1) void gemm_tf32_kernel(
    int mode,
    const float* __restrict__ A,
    const float* __restrict__ Bsrc,
    const float* __restrict__ bias,
    float* __restrict__ out)
{
    extern __shared__ float sm[];
    float* Asm = sm;                 // [2][128*36]
    float* Bsm = sm + 2 * 4608;      // [2][128*36]

    const int tid  = threadIdx.x;
    const int lane = tid & 31;
    const int wid  = tid >> 5;
    const int wm   = (wid >> 2) * 64;
    const int wn   = (wid & 3) * 32;
    const int r    = lane >> 2;
    const int qd   = lane & 3;

    const int m0 = blockIdx.y * 128;
    const int n0 = blockIdx.x * 128;

    float c[4][4][4] = {};

    auto issue = [&](int cidx) {
        const int p  = cidx & 1;
        const int k0 = cidx * 32;
        #pragma unroll
        for (int rr = 0; rr < 4; rr++) {
            int it  = tid + 256 * rr;
            int row = it >> 3;
            int f4  = it & 7;
            uint32_t da = smem_u32(Asm + p * 4608 + row * 36 + f4 * 4);
            CP16(da, A + (size_t)(m0 + row) * EE + k0 + f4 * 4);
            uint32_t db = smem_u32(Bsm + p * 4608 + row * 36 + f4 * 4);
            CP16(db, Bsrc + (size_t)(n0 + row) * EE + k0 + f4 * 4);
        }
        CP_COMMIT();
    };

    issue(0);
    for (int cc = 0; cc < 32; cc++) {
        const int p = cc & 1;
        if (cc + 1 < 32) { issue(cc + 1); CP_WAIT1(); }
        else             { CP_WAIT0(); }
        __syncthreads();

        const float* ap = Asm + p * 4608;
        const float* bp = Bsm + p * 4608;
        #pragma unroll
        for (int k8 = 0; k8 < 4; k8++) {
            const int kk = k8 * 8;
            uint32_t a[4][4];
            #pragma unroll
            for (int i = 0; i < 4; i++) {
                a[i][0] = __float_as_uint(ap[(wm + i * 16 + r)     * 36 + kk + qd]);
                a[i][1] = __float_as_uint(ap[(wm + i * 16 + r + 8) * 36 + kk + qd]);
                a[i][2] = __float_as_uint(ap[(wm + i * 16 + r)     * 36 + kk + qd + 4]);
                a[i][3] = __float_as_uint(ap[(wm + i * 16 + r + 8) * 36 + kk + qd + 4]);
            }
            #pragma unroll
            for (int j = 0; j < 4; j++) {
                uint32_t b0 = __float_as_uint(bp[(wn + j * 8 + r) * 36 + kk + qd]);
                uint32_t b1 = __float_as_uint(bp[(wn + j * 8 + r) * 36 + kk + qd + 4]);
                #pragma unroll
                for (int i = 0; i < 4; i++)
                    mma8(c[i][j], a[i][0], a[i][1], a[i][2], a[i][3], b0, b1);
            }
        }
        __syncthreads();
    }

    // ---- epilogue ----
    #pragma unroll
    for (int i = 0; i < 4; i++) {
        const int gm0 = m0 + wm + i * 16 + r;
        if (mode == 0) {
            const int b = gm0 >> 11;
            const int t = gm0 & 2047;
            #pragma unroll
            for (int j = 0; j < 4; j++) {
                const int col = n0 + wn + j * 8 + qd * 2;
                const int mat = col >> 10;
                const int rem = col & 1023;
                const int h   = rem >> 6;
                const int d   = rem & 63;
                float* base = (mat == 0) ? g_q : (mat == 1 ? g_k : g_v);
                size_t o0 = ((size_t)((b * 16 + h) * 2048 + t)) * 64 + d;
                *(float2*)(base + o0) =
                    make_float2(tf32f(c[i][j][0]), tf32f(c[i][j][1]));
                *(float2*)(base + o0 + 8 * 64) =
                    make_float2(tf32f(c[i][j][2]), tf32f(c[i][j][3]));
            }
        } else {
            #pragma unroll
            for (int j = 0; j < 4; j++) {
                const int col = n0 + wn + j * 8 + qd * 2;
                float2 bv = *(const float2*)(bias + col);
                float* d0 = out + (size_t)gm0 * EE + col;
                *(float2*)d0            = make_float2(c[i][j][0] + bv.x, c[i][j][1] + bv.y);
                *(float2*)(d0 + 8 * EE) = make_float2(c[i][j][2] + bv.x, c[i][j][3] + bv.y);
            }
        }
    }
}

// ---------------------------------------------------------------------------
// Causal flash attention, tf32 mma.sync.
// 256 threads / 8 warps; q-tile 128 (16 rows per warp), k-tile 64.
// Q fragments live in registers; Q's SMEM is reused for P.
// K/V double-buffered via cp.async. Softmax in log2 domain (exp2f).
// SMEM: QP[128*68] + K[2][64*68] + V[2][64*72] = 106496 B  -> 2 blocks/SM.
// ---------------------------------------------------------------------------
#define AM 128
#define AN 64
#define QP_SZ (AM * 68)
#define KS_SZ (AN * 68)
#define VS_SZ (AN * 72)

__global__ __launch_bounds__(256) void attn_kernel()
{
    extern __shared__ float smp[];
    float* QP = smp;                    // Q, later P  [128][68]
    float* K0 = QP + QP_SZ;             // [2][64][68]
    float* V0 = K0 + 2 * KS_SZ;         // [2][64][72]

    const int bh = blockIdx.y;
    const int b  = bh >> 4;
    const int h  = bh & 15;
    const int q0 = TT - AM - blockIdx.x * AM;   // longest first

    const int tid  = threadIdx.x;
    const int lane = tid & 31;
    const int wid  = tid >> 5;
    const int wm   = wid * 16;
    const int r    = lane >> 2;
    const int qd   = lane & 3;

    const float* qg = g_q + ((size_t)bh * TT + q0) * HD;
    const float* kg = g_k + (size_t)bh * TT * HD;
    const float* vg = g_v + (size_t)bh * TT * HD;

    // ---- load Q, scale by 0.125*log2(e), round to tf32 ----
    const float qscale = 0.125f * 1.44269504f;
    for (int it = tid; it < AM * 16; it += 256) {
        int row = it >> 4, f4 = it & 15;
        float4 v = *(const float4*)(qg + (size_t)row * 64 + f4 * 4);
        *(float4*)(QP + row * 68 + f4 * 4) =
            make_float4(tf32f(v.x * qscale), tf32f(v.y * qscale),
                        tf32f(v.z * qscale), tf32f(v.w * qscale));
    }

    // ---- prefetch helper: K/V tile t -> buffer t&1 ----
    auto issueKV = [&](int t) {
        const int p  = t & 1;
        const int s0 = t * 64;
        #pragma unroll
        for (int rr = 0; rr < 4; rr++) {
            int it  = tid + 256 * rr;
            int row = it >> 4;
            int f4  = it & 15;
            uint32_t dk = smem_u32(K0 + p * KS_SZ + row * 68 + f4 * 4);
            CP16(dk, kg + (size_t)(s0 + row) * 64 + f4 * 4);
            uint32_t dv = smem_u32(V0 + p * VS_SZ + row * 72 + f4 * 4);
            CP16(dv, vg + (size_t)(s0 + row) * 64 + f4 * 4);
        }
        CP_COMMIT();
    };

    const int nt = q0 / 64 + 2;          // covers s0 <= q0 + 127
    issueKV(0);

    __syncthreads();                      // Q tile visible

    // ---- hoist Q fragments into registers ----
    uint32_t qa[8][4];
    #pragma unroll
    for (int k8 = 0; k8 < 8; k8++) {
        const int kk = k8 * 8;
        qa[k8][0] = __float_as_uint(QP[(wm + r)     * 68 + kk + qd]);
        qa[k8][1] = __float_as_uint(QP[(wm + r + 8) * 68 + kk + qd]);
        qa[k8][2] = __float_as_uint(QP[(wm + r)     * 68 + kk + qd + 4]);
        qa[k8][3] = __float_as_uint(QP[(wm + r + 8) * 68 + kk + qd + 4]);
    }

    float o[8][4] = {};
    float m0r = -1e30f, m1r = -1e30f, l0 = 0.f, l1 = 0.f;

    for (int t = 0; t < nt; t++) {
        const int p  = t & 1;
        const int s0 = t * 64;
        if (t + 1 < nt) { issueKV(t + 1); CP_WAIT1(); }
        else            { CP_WAIT0(); }
        __syncthreads();

        // warp fully masked for this tile? (min row of warp < min col)
        if (s0 <= q0 + wm + 15) {
            const float* Ks = K0 + p * KS_SZ;
            const float* Vs = V0 + p * VS_SZ;

            // ---- S = Q K^T (16 x 64 per warp), log2-scaled ----
            float c[8][4] = {};
            #pragma unroll
            for (int k8 = 0; k8 < 8; k8++) {
                const int kk = k8 * 8;
                #pragma unroll
                for (int j = 0; j < 8; j++) {
                    uint32_t b0 = __float_as_uint(Ks[(j * 8 + r) * 68 + kk + qd]);
                    uint32_t b1 = __float_as_uint(Ks[(j * 8 + r) * 68 + kk + qd + 4]);
                    mma8(c[j], qa[k8][0], qa[k8][1], qa[k8][2], qa[k8][3], b0, b1);
                }
            }

            // ---- causal mask ----
            if (s0 + 63 > q0 + wm) {
                const int row0 = q0 + wm + r, row1 = row0 + 8;
                #pragma unroll
                for (int j = 0; j < 8; j++) {
                    const int cl = s0 + j * 8 + qd * 2;
                    if (cl     > row0) c[j][0] = -1e30f;
                    if (cl + 1 > row0) c[j][1] = -1e30f;
                    if (cl     > row1) c[j][2] = -1e30f;
                    if (cl + 1 > row1) c[j][3] = -1e30f;
                }
            }

            // ---- online softmax (base-2) ----
            float mx0 = -1e30f, mx1 = -1e30f;
            #pragma unroll
            for (int j = 0; j < 8; j++) {
                mx0 = fmaxf(mx0, fmaxf(c[j][0], c[j][1]));
                mx1 = fmaxf(mx1, fmaxf(c[j][2], c[j][3]));
            }
            mx0 = fmaxf(mx0, __shfl_xor_sync(0xffffffffu, mx0, 1));
            mx0 = fmaxf(mx0, __shfl_xor_sync(0xffffffffu, mx0, 2));
            mx1 = fmaxf(mx1, __shfl_xor_sync(0xffffffffu, mx1, 1));
            mx1 = fmaxf(mx1, __shfl_xor_sync(0xffffffffu, mx1, 2));

            const float nm0 = fmaxf(m0r, mx0), nm1 = fmaxf(m1r, mx1);
            const float f0 = exp2f(m0r - nm0), f1 = exp2f(m1r - nm1);
            float rs0 = 0.f, rs1 = 0.f;
            #pragma unroll
            for (int j = 0; j < 8; j++) {
                c[j][0] = exp2f(c[j][0] - nm0);
                c[j][1] = exp2f(c[j][1] - nm0);
                c[j][2] = exp2f(c[j][2] - nm1);
                c[j][3] = exp2f(c[j][3] - nm1);
                rs0 += c[j][0] + c[j][1];
                rs1 += c[j][2] + c[j][3];
            }
            rs0 += __shfl_xor_sync(0xffffffffu, rs0, 1);
            rs0 += __shfl_xor_sync(0xffffffffu, rs0, 2);
            rs1 += __shfl_xor_sync(0xffffffffu, rs1, 1);
            rs1 += __shfl_xor_sync(0xffffffffu, rs1, 2);

            l0 = l0 * f0 + rs0;  m0r = nm0;
            l1 = l1 * f1 + rs1;  m1r = nm1;
            #pragma unroll
            for (int j = 0; j < 8; j++) {
                o[j][0] *= f0;  o[j][1] *= f0;
                o[j][2] *= f1;  o[j][3] *= f1;
            }

            // ---- P -> warp-private SMEM rows (raw f32; mma truncates) ----
            #pragma unroll
            for (int j = 0; j < 8; j++) {
                *(float2*)(QP + (wm + r)     * 68 + j * 8 + qd * 2) =
                    make_float2(c[j][0], c[j][1]);
                *(float2*)(QP + (wm + r + 8) * 68 + j * 8 + qd * 2) =
                    make_float2(c[j][2], c[j][3]);
            }
            __syncwarp();

            // ---- O += P V ----
            #pragma unroll
            for (int k8 = 0; k8 < 8; k8++) {
                const int kk = k8 * 8;
                uint32_t a0 = __float_as_uint(QP[(wm + r)     * 68 + kk + qd]);
                uint32_t a1 = __float_as_uint(QP[(wm + r + 8) * 68 + kk + qd]);
                uint32_t a2 = __float_as_uint(QP[(wm + r)     * 68 + kk + qd + 4]);
                uint32_t a3 = __float_as_uint(QP[(wm + r + 8) * 68 + kk + qd + 4]);
                #pragma unroll
                for (int j = 0; j < 8; j++) {
                    uint32_t b0 = __float_as_uint(Vs[(kk + qd)     * 72 + j * 8 + r]);
                    uint32_t b1 = __float_as_uint(Vs[(kk + qd + 4) * 72 + j * 8 + r]);
                    mma8(o[j], a0, a1, a2, a3, b0, b1);
                }
            }
        }
        __syncthreads();   // compute done before buffer t&1 is overwritten
    }

    // ---- epilogue: normalize, round to tf32 (feeds oproj), store ----
    const float inv0 = 1.0f / l0, inv1 = 1.0f / l1;
    const int t0 = q0 + wm + r;
    float* og0 = g_att + ((size_t)b * TT + t0) * EE + h * 64;
    float* og1 = og0 + 8 * EE;
    #pragma unroll
    for (int j = 0; j < 8; j++) {
        *(float2*)(og0 + j * 8 + qd * 2) =
            make_float2(tf32f(o[j][0] * inv0), tf32f(o[j][1] * inv0));
        *(float2*)(og1 + j * 8 + qd * 2) =
            make_float2(tf32f(o[j][2] * inv1), tf32f(o[j][3] * inv1));
    }
}

// ---------------------------------------------------------------------------
extern "C" void kernel_launch(void* const* d_in, const int* in_sizes, int n_in,
                              void* d_out, int out_size)
{
    const float* x  = (const float*)d_in[0];
    const float* Wq = (const float*)d_in[1];
    const float* Wk = (const float*)d_in[2];
    const float* Wv = (const float*)d_in[3];
    const float* Wo = (const float*)d_in[4];
    const float* bo = (const float*)d_in[5];
    float* out = (float*)d_out;

    float *wt_ptr, *att_ptr, *xr_ptr, *wo_ptr;
    cudaGetSymbolAddress((void**)&wt_ptr,  g_wt);
    cudaGetSymbolAddress((void**)&att_ptr, g_att);
    cudaGetSymbolAddress((void**)&xr_ptr,  g_xr);
    cudaGetSymbolAddress((void**)&wo_ptr,  g_wo);

    // 1) pre-round x and Wo; pack+round per-head weights
    {
        int n4x = BB * TT * EE / 4;
        round_kernel<<<(n4x + 255) / 256, 256>>>((const float4*)x, (float4*)xr_ptr, n4x);
        int n4w = EE * EE / 4;
        round_kernel<<<(n4w + 255) / 256, 256>>>((const float4*)Wo, (float4*)wo_ptr, n4w);
        dim3 grid(EE / 32, HH * 2, 3);
        dim3 blk(32, 8);
        wt_transpose_kernel<<<grid, blk>>>(Wq, Wk, Wv);
    }

    const int gemm_smem = 4 * 4608 * sizeof(float);                 // 73728 B
    cudaFuncSetAttribute(gemm_tf32_kernel,
                         cudaFuncAttributeMaxDynamicSharedMemorySize, gemm_smem);
    const int attn_smem = (QP_SZ + 2 * KS_SZ + 2 * VS_SZ) * sizeof(float); // 106496 B
    cudaFuncSetAttribute(attn_kernel,
                         cudaFuncAttributeMaxDynamicSharedMemorySize, attn_smem);

    // 2) QKV: [8192,3072] = g_xr @ g_wt^T  (rounded scatter -> g_q/g_k/g_v)
    {
        dim3 grid(3 * EE / 128, (BB * TT) / 128);   // (24, 64)
        gemm_tf32_kernel<<<grid, 256, gemm_smem>>>(0, xr_ptr, wt_ptr, nullptr, nullptr);
    }

    // 3) attention
    {
        dim3 gridB(TT / AM, BB * HH);               // (16, 64)
        attn_kernel<<<gridB, 256, attn_smem>>>();
    }

    // 4) O projection: out = g_att @ g_wo^T + bo
    {
        dim3 grid(EE / 128, (BB * TT) / 128);       // (8, 64)
        gemm_tf32_kernel<<<grid, 256, gemm_smem>>>(1, att_ptr, wo_ptr, bo, out);
    }
}

// round 6
// speedup vs baseline: 3.8664x; 1.0866x over previous
#include <cuda_runtime.h>
#include <cstdint>

#define BB 4
#define TT 2048
#define EE 1024
#define HH 16
#define HD 64

// ---------------------------------------------------------------------------
// Scratch (device globals; no allocation allowed anywhere). 16B-aligned.
// ---------------------------------------------------------------------------
__device__ __align__(16) float g_q[BB * HH * TT * HD];   // [B,H,T,HD] (tf32-rounded)
__device__ __align__(16) float g_k[BB * HH * TT * HD];
__device__ __align__(16) float g_v[BB * HH * TT * HD];
__device__ __align__(16) float g_att[BB * TT * EE];      // [B,T,E]   (tf32-rounded)
__device__ __align__(16) float g_wt[3 * EE * EE];        // K-major weights (rounded)
__device__ __align__(16) float g_xr[BB * TT * EE];       // rounded x
__device__ __align__(16) float g_wo[EE * EE];            // rounded Wo

// ---------------------------------------------------------------------------
// Helpers
// ---------------------------------------------------------------------------
__device__ __forceinline__ uint32_t smem_u32(const void* p) {
    uint32_t a;
    asm("{ .reg .u64 t; cvta.to.shared.u64 t, %1; cvt.u32.u64 %0, t; }"
        : "=r"(a) : "l"(p));
    return a;
}

__device__ __forceinline__ uint32_t t32(float x) {
    uint32_t u;
    asm("cvt.rna.tf32.f32 %0, %1;" : "=r"(u) : "f"(x));
    return u;
}
__device__ __forceinline__ float tf32f(float x) { return __uint_as_float(t32(x)); }

__device__ __forceinline__ void mma8(float c[4],
                                     uint32_t a0, uint32_t a1, uint32_t a2, uint32_t a3,
                                     uint32_t b0, uint32_t b1) {
    asm volatile(
        "mma.sync.aligned.m16n8k8.row.col.f32.tf32.tf32.f32 "
        "{%0,%1,%2,%3},{%4,%5,%6,%7},{%8,%9},{%0,%1,%2,%3};"
        : "+f"(c[0]), "+f"(c[1]), "+f"(c[2]), "+f"(c[3])
        : "r"(a0), "r"(a1), "r"(a2), "r"(a3), "r"(b0), "r"(b1));
}

#define CP16(dst, src) \
    asm volatile("cp.async.cg.shared.global [%0], [%1], 16;" :: "r"(dst), "l"(src))
#define CP_COMMIT()  asm volatile("cp.async.commit_group;" ::: "memory")
#define CP_WAIT1()   asm volatile("cp.async.wait_group 1;" ::: "memory")
#define CP_WAIT0()   asm volatile("cp.async.wait_group 0;" ::: "memory")

// ---------------------------------------------------------------------------
// tf32 pre-rounding pass (vectorized). n4 = element count / 4.
// ---------------------------------------------------------------------------
__global__ __launch_bounds__(256) void round_kernel(const float4* __restrict__ src,
                                                    float4* __restrict__ dst, int n4)
{
    int i = blockIdx.x * 256 + threadIdx.x;
    if (i < n4) {
        float4 v = src[i];
        dst[i] = make_float4(tf32f(v.x), tf32f(v.y), tf32f(v.z), tf32f(v.w));
    }
}

// ---------------------------------------------------------------------------
// Weight transpose + round: g_wt[n][k] = round(W_m[h][k][d]), n = m*1024+h*64+d
// ---------------------------------------------------------------------------
__global__ __launch_bounds__(256) void wt_transpose_kernel(
    const float* __restrict__ Wq,
    const float* __restrict__ Wk,
    const float* __restrict__ Wv)
{
    const float* Ws[3] = {Wq, Wk, Wv};
    const int m  = blockIdx.z;
    const int h  = blockIdx.y >> 1;
    const int d0 = (blockIdx.y & 1) * 32;
    const int k0 = blockIdx.x * 32;

    __shared__ float tile[32][33];
    const int tx = threadIdx.x;   // 0..31
    const int ty = threadIdx.y;   // 0..7

    const float* src = Ws[m] + (size_t)h * EE * HD;
    #pragma unroll
    for (int i = 0; i < 4; i++)
        tile[ty + 8 * i][tx] = src[(size_t)(k0 + ty + 8 * i) * HD + d0 + tx];
    __syncthreads();

    #pragma unroll
    for (int i = 0; i < 4; i++) {
        int n = m * 1024 + h * 64 + d0 + ty + 8 * i;
        g_wt[(size_t)n * EE + k0 + tx] = tf32f(tile[tx][ty + 8 * i]);
    }
}

// ---------------------------------------------------------------------------
// tf32 mma.sync GEMM:  C[M,N] = A[M,K] @ B[N,K]^T.  Inputs pre-rounded to tf32
// so the inner loop does raw LDS (MMA truncation is exact).
// Block tile 128x128, K-chunk 32 (stride 36 => conflict-free), cp.async x2.
// __launch_bounds__(256,2): cap regs at 128 so TWO blocks co-reside per SM —
// round-5 ncu showed occ=12.5% (1 block/SM) leaving the tensor pipe idle at
// every barrier.
// mode 0: QKV  (A=g_xr, B=g_wt, scatter rounded -> g_q/g_k/g_v)
// mode 1: OPROJ(A=g_att, B=g_wo, out = C + bo)
// ---------------------------------------------------------------------------
__global__ __launch_bounds__(256, 2) void gemm_tf32_kernel(
    int mode,
    const float* __restrict__ A,
    const float* __restrict__ Bsrc,
    const float* __restrict__ bias,
    float* __restrict__ out)
{
    extern __shared__ float sm[];
    float* Asm = sm;                 // [2][128*36]
    float* Bsm = sm + 2 * 4608;      // [2][128*36]

    const int tid  = threadIdx.x;
    const int lane = tid & 31;
    const int wid  = tid >> 5;
    const int wm   = (wid >> 2) * 64;
    const int wn   = (wid & 3) * 32;
    const int r    = lane >> 2;
    const int qd   = lane & 3;

    const int m0 = blockIdx.y * 128;
    const int n0 = blockIdx.x * 128;

    float c[4][4][4] = {};

    auto issue = [&](int cidx) {
        const int p  = cidx & 1;
        const int k0 = cidx * 32;
        #pragma unroll
        for (int rr = 0; rr < 4; rr++) {
            int it  = tid + 256 * rr;
            int row = it >> 3;
            int f4  = it & 7;
            uint32_t da = smem_u32(Asm + p * 4608 + row * 36 + f4 * 4);
            CP16(da, A + (size_t)(m0 + row) * EE + k0 + f4 * 4);
            uint32_t db = smem_u32(Bsm + p * 4608 + row * 36 + f4 * 4);
            CP16(db, Bsrc + (size_t)(n0 + row) * EE + k0 + f4 * 4);
        }
        CP_COMMIT();
    };

    issue(0);
    for (int cc = 0; cc < 32; cc++) {
        const int p = cc & 1;
        if (cc + 1 < 32) { issue(cc + 1); CP_WAIT1(); }
        else             { CP_WAIT0(); }
        __syncthreads();

        const float* ap = Asm + p * 4608;
        const float* bp = Bsm + p * 4608;
        #pragma unroll
        for (int k8 = 0; k8 < 4; k8++) {
            const int kk = k8 * 8;
            uint32_t a[4][4];
            #pragma unroll
            for (int i = 0; i < 4; i++) {
                a[i][0] = __float_as_uint(ap[(wm + i * 16 + r)     * 36 + kk + qd]);
                a[i][1] = __float_as_uint(ap[(wm + i * 16 + r + 8) * 36 + kk + qd]);
                a[i][2] = __float_as_uint(ap[(wm + i * 16 + r)     * 36 + kk + qd + 4]);
                a[i][3] = __float_as_uint(ap[(wm + i * 16 + r + 8) * 36 + kk + qd + 4]);
            }
            #pragma unroll
            for (int j = 0; j < 4; j++) {
                uint32_t b0 = __float_as_uint(bp[(wn + j * 8 + r) * 36 + kk + qd]);
                uint32_t b1 = __float_as_uint(bp[(wn + j * 8 + r) * 36 + kk + qd + 4]);
                #pragma unroll
                for (int i = 0; i < 4; i++)
                    mma8(c[i][j], a[i][0], a[i][1], a[i][2], a[i][3], b0, b1);
            }
        }
        __syncthreads();
    }

    // ---- epilogue ----
    #pragma unroll
    for (int i = 0; i < 4; i++) {
        const int gm0 = m0 + wm + i * 16 + r;
        if (mode == 0) {
            const int b = gm0 >> 11;
            const int t = gm0 & 2047;
            #pragma unroll
            for (int j = 0; j < 4; j++) {
                const int col = n0 + wn + j * 8 + qd * 2;
                const int mat = col >> 10;
                const int rem = col & 1023;
                const int h   = rem >> 6;
                const int d   = rem & 63;
                float* base = (mat == 0) ? g_q : (mat == 1 ? g_k : g_v);
                size_t o0 = ((size_t)((b * 16 + h) * 2048 + t)) * 64 + d;
                *(float2*)(base + o0) =
                    make_float2(tf32f(c[i][j][0]), tf32f(c[i][j][1]));
                *(float2*)(base + o0 + 8 * 64) =
                    make_float2(tf32f(c[i][j][2]), tf32f(c[i][j][3]));
            }
        } else {
            #pragma unroll
            for (int j = 0; j < 4; j++) {
                const int col = n0 + wn + j * 8 + qd * 2;
                float2 bv = *(const float2*)(bias + col);
                float* d0 = out + (size_t)gm0 * EE + col;
                *(float2*)d0            = make_float2(c[i][j][0] + bv.x, c[i][j][1] + bv.y);
                *(float2*)(d0 + 8 * EE) = make_float2(c[i][j][2] + bv.x, c[i][j][3] + bv.y);
            }
        }
    }
}

// ---------------------------------------------------------------------------
// Causal flash attention, tf32 mma.sync.
// 256 threads / 8 warps; q-tile 128 (16 rows per warp), k-tile 64.
// Q fragments live in registers; Q's SMEM is reused for P.
// K/V double-buffered via cp.async. Softmax in log2 domain (exp2f).
// SMEM: QP[128*68] + K[2][64*68] + V[2][64*72] = 106496 B.
// __launch_bounds__(256,2): two blocks per SM (212992 B <= 228 KB smem).
// ---------------------------------------------------------------------------
#define AM 128
#define AN 64
#define QP_SZ (AM * 68)
#define KS_SZ (AN * 68)
#define VS_SZ (AN * 72)

__global__ __launch_bounds__(256, 2) void attn_kernel()
{
    extern __shared__ float smp[];
    float* QP = smp;                    // Q, later P  [128][68]
    float* K0 = QP + QP_SZ;             // [2][64][68]
    float* V0 = K0 + 2 * KS_SZ;         // [2][64][72]

    const int bh = blockIdx.y;
    const int b  = bh >> 4;
    const int h  = bh & 15;
    const int q0 = TT - AM - blockIdx.x * AM;   // longest first

    const int tid  = threadIdx.x;
    const int lane = tid & 31;
    const int wid  = tid >> 5;
    const int wm   = wid * 16;
    const int r    = lane >> 2;
    const int qd   = lane & 3;

    const float* qg = g_q + ((size_t)bh * TT + q0) * HD;
    const float* kg = g_k + (size_t)bh * TT * HD;
    const float* vg = g_v + (size_t)bh * TT * HD;

    // ---- load Q, scale by 0.125*log2(e), round to tf32 ----
    const float qscale = 0.125f * 1.44269504f;
    for (int it = tid; it < AM * 16; it += 256) {
        int row = it >> 4, f4 = it & 15;
        float4 v = *(const float4*)(qg + (size_t)row * 64 + f4 * 4);
        *(float4*)(QP + row * 68 + f4 * 4) =
            make_float4(tf32f(v.x * qscale), tf32f(v.y * qscale),
                        tf32f(v.z * qscale), tf32f(v.w * qscale));
    }

    // ---- prefetch helper: K/V tile t -> buffer t&1 ----
    auto issueKV = [&](int t) {
        const int p  = t & 1;
        const int s0 = t * 64;
        #pragma unroll
        for (int rr = 0; rr < 4; rr++) {
            int it  = tid + 256 * rr;
            int row = it >> 4;
            int f4  = it & 15;
            uint32_t dk = smem_u32(K0 + p * KS_SZ + row * 68 + f4 * 4);
            CP16(dk, kg + (size_t)(s0 + row) * 64 + f4 * 4);
            uint32_t dv = smem_u32(V0 + p * VS_SZ + row * 72 + f4 * 4);
            CP16(dv, vg + (size_t)(s0 + row) * 64 + f4 * 4);
        }
        CP_COMMIT();
    };

    const int nt = q0 / 64 + 2;          // covers s0 <= q0 + 127
    issueKV(0);

    __syncthreads();                      // Q tile visible

    // ---- hoist Q fragments into registers ----
    uint32_t qa[8][4];
    #pragma unroll
    for (int k8 = 0; k8 < 8; k8++) {
        const int kk = k8 * 8;
        qa[k8][0] = __float_as_uint(QP[(wm + r)     * 68 + kk + qd]);
        qa[k8][1] = __float_as_uint(QP[(wm + r + 8) * 68 + kk + qd]);
        qa[k8][2] = __float_as_uint(QP[(wm + r)     * 68 + kk + qd + 4]);
        qa[k8][3] = __float_as_uint(QP[(wm + r + 8) * 68 + kk + qd + 4]);
    }

    float o[8][4] = {};
    float m0r = -1e30f, m1r = -1e30f, l0 = 0.f, l1 = 0.f;

    for (int t = 0; t < nt; t++) {
        const int p  = t & 1;
        const int s0 = t * 64;
        if (t + 1 < nt) { issueKV(t + 1); CP_WAIT1(); }
        else            { CP_WAIT0(); }
        __syncthreads();

        // warp fully masked for this tile? (min row of warp < min col)
        if (s0 <= q0 + wm + 15) {
            const float* Ks = K0 + p * KS_SZ;
            const float* Vs = V0 + p * VS_SZ;

            // ---- S = Q K^T (16 x 64 per warp), log2-scaled ----
            float c[8][4] = {};
            #pragma unroll
            for (int k8 = 0; k8 < 8; k8++) {
                const int kk = k8 * 8;
                #pragma unroll
                for (int j = 0; j < 8; j++) {
                    uint32_t b0 = __float_as_uint(Ks[(j * 8 + r) * 68 + kk + qd]);
                    uint32_t b1 = __float_as_uint(Ks[(j * 8 + r) * 68 + kk + qd + 4]);
                    mma8(c[j], qa[k8][0], qa[k8][1], qa[k8][2], qa[k8][3], b0, b1);
                }
            }

            // ---- causal mask ----
            if (s0 + 63 > q0 + wm) {
                const int row0 = q0 + wm + r, row1 = row0 + 8;
                #pragma unroll
                for (int j = 0; j < 8; j++) {
                    const int cl = s0 + j * 8 + qd * 2;
                    if (cl     > row0) c[j][0] = -1e30f;
                    if (cl + 1 > row0) c[j][1] = -1e30f;
                    if (cl     > row1) c[j][2] = -1e30f;
                    if (cl + 1 > row1) c[j][3] = -1e30f;
                }
            }

            // ---- online softmax (base-2) ----
            float mx0 = -1e30f, mx1 = -1e30f;
            #pragma unroll
            for (int j = 0; j < 8; j++) {
                mx0 = fmaxf(mx0, fmaxf(c[j][0], c[j][1]));
                mx1 = fmaxf(mx1, fmaxf(c[j][2], c[j][3]));
            }
            mx0 = fmaxf(mx0, __shfl_xor_sync(0xffffffffu, mx0, 1));
            mx0 = fmaxf(mx0, __shfl_xor_sync(0xffffffffu, mx0, 2));
            mx1 = fmaxf(mx1, __shfl_xor_sync(0xffffffffu, mx1, 1));
            mx1 = fmaxf(mx1, __shfl_xor_sync(0xffffffffu, mx1, 2));

            const float nm0 = fmaxf(m0r, mx0), nm1 = fmaxf(m1r, mx1);
            const float f0 = exp2f(m0r - nm0), f1 = exp2f(m1r - nm1);
            float rs0 = 0.f, rs1 = 0.f;
            #pragma unroll
            for (int j = 0; j < 8; j++) {
                c[j][0] = exp2f(c[j][0] - nm0);
                c[j][1] = exp2f(c[j][1] - nm0);
                c[j][2] = exp2f(c[j][2] - nm1);
                c[j][3] = exp2f(c[j][3] - nm1);
                rs0 += c[j][0] + c[j][1];
                rs1 += c[j][2] + c[j][3];
            }
            rs0 += __shfl_xor_sync(0xffffffffu, rs0, 1);
            rs0 += __shfl_xor_sync(0xffffffffu, rs0, 2);
            rs1 += __shfl_xor_sync(0xffffffffu, rs1, 1);
            rs1 += __shfl_xor_sync(0xffffffffu, rs1, 2);

            l0 = l0 * f0 + rs0;  m0r = nm0;
            l1 = l1 * f1 + rs1;  m1r = nm1;
            #pragma unroll
            for (int j = 0; j < 8; j++) {
                o[j][0] *= f0;  o[j][1] *= f0;
                o[j][2] *= f1;  o[j][3] *= f1;
            }

            // ---- P -> warp-private SMEM rows (raw f32; mma truncates) ----
            #pragma unroll
            for (int j = 0; j < 8; j++) {
                *(float2*)(QP + (wm + r)     * 68 + j * 8 + qd * 2) =
                    make_float2(c[j][0], c[j][1]);
                *(float2*)(QP + (wm + r + 8) * 68 + j * 8 + qd * 2) =
                    make_float2(c[j][2], c[j][3]);
            }
            __syncwarp();

            // ---- O += P V ----
            #pragma unroll
            for (int k8 = 0; k8 < 8; k8++) {
                const int kk = k8 * 8;
                uint32_t a0 = __float_as_uint(QP[(wm + r)     * 68 + kk + qd]);
                uint32_t a1 = __float_as_uint(QP[(wm + r + 8) * 68 + kk + qd]);
                uint32_t a2 = __float_as_uint(QP[(wm + r)     * 68 + kk + qd + 4]);
                uint32_t a3 = __float_as_uint(QP[(wm + r + 8) * 68 + kk + qd + 4]);
                #pragma unroll
                for (int j = 0; j < 8; j++) {
                    uint32_t b0 = __float_as_uint(Vs[(kk + qd)     * 72 + j * 8 + r]);
                    uint32_t b1 = __float_as_uint(Vs[(kk + qd + 4) * 72 + j * 8 + r]);
                    mma8(o[j], a0, a1, a2, a3, b0, b1);
                }
            }
        }
        __syncthreads();   // compute done before buffer t&1 is overwritten
    }

    // ---- epilogue: normalize, round to tf32 (feeds oproj), store ----
    const float inv0 = 1.0f / l0, inv1 = 1.0f / l1;
    const int t0 = q0 + wm + r;
    float* og0 = g_att + ((size_t)b * TT + t0) * EE + h * 64;
    float* og1 = og0 + 8 * EE;
    #pragma unroll
    for (int j = 0; j < 8; j++) {
        *(float2*)(og0 + j * 8 + qd * 2) =
            make_float2(tf32f(o[j][0] * inv0), tf32f(o[j][1] * inv0));
        *(float2*)(og1 + j * 8 + qd * 2) =
            make_float2(tf32f(o[j][2] * inv1), tf32f(o[j][3] * inv1));
    }
}

// ---------------------------------------------------------------------------
extern "C" void kernel_launch(void* const* d_in, const int* in_sizes, int n_in,
                              void* d_out, int out_size)
{
    const float* x  = (const float*)d_in[0];
    const float* Wq = (const float*)d_in[1];
    const float* Wk = (const float*)d_in[2];
    const float* Wv = (const float*)d_in[3];
    const float* Wo = (const float*)d_in[4];
    const float* bo = (const float*)d_in[5];
    float* out = (float*)d_out;

    float *wt_ptr, *att_ptr, *xr_ptr, *wo_ptr;
    cudaGetSymbolAddress((void**)&wt_ptr,  g_wt);
    cudaGetSymbolAddress((void**)&att_ptr, g_att);
    cudaGetSymbolAddress((void**)&xr_ptr,  g_xr);
    cudaGetSymbolAddress((void**)&wo_ptr,  g_wo);

    // 1) pre-round x and Wo; pack+round per-head weights
    {
        int n4x = BB * TT * EE / 4;
        round_kernel<<<(n4x + 255) / 256, 256>>>((const float4*)x, (float4*)xr_ptr, n4x);
        int n4w = EE * EE / 4;
        round_kernel<<<(n4w + 255) / 256, 256>>>((const float4*)Wo, (float4*)wo_ptr, n4w);
        dim3 grid(EE / 32, HH * 2, 3);
        dim3 blk(32, 8);
        wt_transpose_kernel<<<grid, blk>>>(Wq, Wk, Wv);
    }

    const int gemm_smem = 4 * 4608 * sizeof(float);                 // 73728 B
    cudaFuncSetAttribute(gemm_tf32_kernel,
                         cudaFuncAttributeMaxDynamicSharedMemorySize, gemm_smem);
    const int attn_smem = (QP_SZ + 2 * KS_SZ + 2 * VS_SZ) * sizeof(float); // 106496 B
    cudaFuncSetAttribute(attn_kernel,
                         cudaFuncAttributeMaxDynamicSharedMemorySize, attn_smem);

    // 2) QKV: [8192,3072] = g_xr @ g_wt^T  (rounded scatter -> g_q/g_k/g_v)
    {
        dim3 grid(3 * EE / 128, (BB * TT) / 128);   // (24, 64)
        gemm_tf32_kernel<<<grid, 256, gemm_smem>>>(0, xr_ptr, wt_ptr, nullptr, nullptr);
    }

    // 3) attention
    {
        dim3 gridB(TT / AM, BB * HH);               // (16, 64)
        attn_kernel<<<gridB, 256, attn_smem>>>();
    }

    // 4) O projection: out = g_att @ g_wo^T + bo
    {
        dim3 grid(EE / 128, (BB * TT) / 128);       // (8, 64)
        gemm_tf32_kernel<<<grid, 256, gemm_smem>>>(1, att_ptr, wo_ptr, bo, out);
    }
}

// round 7
// speedup vs baseline: 7.1751x; 1.8558x over previous
#include <cuda_runtime.h>
#include <cuda_fp16.h>
#include <cstdint>

#define BB 4
#define TT 2048
#define EE 1024
#define HH 16
#define HD 64

// softmax scale folded into Q at QKV epilogue: 1/sqrt(64) * log2(e)
#define QSCALE (0.125f * 1.44269504f)

// ---------------------------------------------------------------------------
// Scratch (device globals). All activations/weights stored fp16.
// ---------------------------------------------------------------------------
__device__ __align__(16) __half g_qh[BB * HH * TT * HD];   // [B,H,T,HD], pre-scaled
__device__ __align__(16) __half g_kh[BB * HH * TT * HD];
__device__ __align__(16) __half g_vh[BB * HH * TT * HD];
__device__ __align__(16) __half g_atth[BB * TT * EE];      // [B,T,E]
__device__ __align__(16) __half g_wth[3 * EE * EE];        // K-major qkv weights
__device__ __align__(16) __half g_xh[BB * TT * EE];        // x in fp16
__device__ __align__(16) __half g_woh[EE * EE];            // Wo in fp16

// ---------------------------------------------------------------------------
// Helpers
// ---------------------------------------------------------------------------
__device__ __forceinline__ uint32_t smem_u32(const void* p) {
    uint32_t a;
    asm("{ .reg .u64 t; cvta.to.shared.u64 t, %1; cvt.u32.u64 %0, t; }"
        : "=r"(a) : "l"(p));
    return a;
}

__device__ __forceinline__ uint32_t f2h2(float lo, float hi) {
    __half2 h = __floats2half2_rn(lo, hi);
    return *(uint32_t*)&h;
}

// m16n8k16 f16 MMA, f32 accumulate
__device__ __forceinline__ void mma16(float c[4],
                                      uint32_t a0, uint32_t a1, uint32_t a2, uint32_t a3,
                                      uint32_t b0, uint32_t b1) {
    asm volatile(
        "mma.sync.aligned.m16n8k16.row.col.f32.f16.f16.f32 "
        "{%0,%1,%2,%3},{%4,%5,%6,%7},{%8,%9},{%0,%1,%2,%3};"
        : "+f"(c[0]), "+f"(c[1]), "+f"(c[2]), "+f"(c[3])
        : "r"(a0), "r"(a1), "r"(a2), "r"(a3), "r"(b0), "r"(b1));
}

#define CP16(dst, src) \
    asm volatile("cp.async.cg.shared.global [%0], [%1], 16;" :: "r"(dst), "l"(src))
#define CP_COMMIT()  asm volatile("cp.async.commit_group;" ::: "memory")
#define CP_WAIT1()   asm volatile("cp.async.wait_group 1;" ::: "memory")
#define CP_WAIT0()   asm volatile("cp.async.wait_group 0;" ::: "memory")

// ---------------------------------------------------------------------------
// fp16 conversion pass: float4 -> 4 halves (as uint2). n4 = count/4.
// ---------------------------------------------------------------------------
__global__ __launch_bounds__(256) void to_half_kernel(const float4* __restrict__ src,
                                                      uint2* __restrict__ dst, int n4)
{
    int i = blockIdx.x * 256 + threadIdx.x;
    if (i < n4) {
        float4 v = src[i];
        dst[i] = make_uint2(f2h2(v.x, v.y), f2h2(v.z, v.w));
    }
}

// ---------------------------------------------------------------------------
// Weight transpose + half: g_wth[n][k] = h(W_m[h][k][d]), n = m*1024+h*64+d
// ---------------------------------------------------------------------------
__global__ __launch_bounds__(256) void wt_transpose_kernel(
    const float* __restrict__ Wq,
    const float* __restrict__ Wk,
    const float* __restrict__ Wv)
{
    const float* Ws[3] = {Wq, Wk, Wv};
    const int m  = blockIdx.z;
    const int h  = blockIdx.y >> 1;
    const int d0 = (blockIdx.y & 1) * 32;
    const int k0 = blockIdx.x * 32;

    __shared__ float tile[32][33];
    const int tx = threadIdx.x;   // 0..31
    const int ty = threadIdx.y;   // 0..7

    const float* src = Ws[m] + (size_t)h * EE * HD;
    #pragma unroll
    for (int i = 0; i < 4; i++)
        tile[ty + 8 * i][tx] = src[(size_t)(k0 + ty + 8 * i) * HD + d0 + tx];
    __syncthreads();

    #pragma unroll
    for (int i = 0; i < 4; i++) {
        int n = m * 1024 + h * 64 + d0 + ty + 8 * i;
        g_wth[(size_t)n * EE + k0 + tx] = __float2half_rn(tile[tx][ty + 8 * i]);
    }
}

// ---------------------------------------------------------------------------
// fp16 mma.sync GEMM:  C[M,N] = A[M,K] @ B[N,K]^T, f32 accumulate.
// Block tile 128x128, K-chunk 64 halves (=128B rows), cp.async double buffer.
// SMEM stride 72 halves (36 words -> conflict-free fragment LDS: bank=4r+qd+8s).
// mode 0: QKV  (A=g_xh, B=g_wth; scatter half -> g_qh(*QSCALE)/g_kh/g_vh)
// mode 1: OPROJ(A=g_atth, B=g_woh; out = C + bo, f32)
// ---------------------------------------------------------------------------
#define SA 72
#define ABUF (128 * SA)

__global__ __launch_bounds__(256, 2) void gemm_h_kernel(
    int mode,
    const __half* __restrict__ A,
    const __half* __restrict__ Bsrc,
    const float* __restrict__ bias,
    float* __restrict__ out)
{
    extern __shared__ __half smh[];
    __half* Ah = smh;                 // [2][128*72]
    __half* Bh = smh + 2 * ABUF;      // [2][128*72]

    const int tid  = threadIdx.x;
    const int lane = tid & 31;
    const int wid  = tid >> 5;
    const int wm   = (wid >> 2) * 64;
    const int wn   = (wid & 3) * 32;
    const int r    = lane >> 2;
    const int qd   = lane & 3;

    const int m0 = blockIdx.y * 128;
    const int n0 = blockIdx.x * 128;

    float c[4][4][4] = {};

    auto issue = [&](int cidx) {
        const int p  = cidx & 1;
        const int k0 = cidx * 64;
        #pragma unroll
        for (int rr = 0; rr < 4; rr++) {
            int it  = tid + 256 * rr;
            int row = it >> 3;
            int c8  = it & 7;
            uint32_t da = smem_u32(Ah + p * ABUF + row * SA + c8 * 8);
            CP16(da, A + (size_t)(m0 + row) * EE + k0 + c8 * 8);
            uint32_t db = smem_u32(Bh + p * ABUF + row * SA + c8 * 8);
            CP16(db, Bsrc + (size_t)(n0 + row) * EE + k0 + c8 * 8);
        }
        CP_COMMIT();
    };

    issue(0);
    for (int cc = 0; cc < 16; cc++) {
        const int p = cc & 1;
        if (cc + 1 < 16) { issue(cc + 1); CP_WAIT1(); }
        else             { CP_WAIT0(); }
        __syncthreads();

        const __half* ap = Ah + p * ABUF;
        const __half* bp = Bh + p * ABUF;
        #pragma unroll
        for (int s = 0; s < 4; s++) {
            uint32_t a[4][4];
            #pragma unroll
            for (int i = 0; i < 4; i++) {
                const __half* arow = ap + (wm + i * 16 + r) * SA + s * 16 + 2 * qd;
                a[i][0] = *(const uint32_t*)(arow);
                a[i][1] = *(const uint32_t*)(arow + 8 * SA);
                a[i][2] = *(const uint32_t*)(arow + 8);
                a[i][3] = *(const uint32_t*)(arow + 8 * SA + 8);
            }
            #pragma unroll
            for (int j = 0; j < 4; j++) {
                const __half* brow = bp + (wn + j * 8 + r) * SA + s * 16 + 2 * qd;
                uint32_t b0 = *(const uint32_t*)(brow);
                uint32_t b1 = *(const uint32_t*)(brow + 8);
                #pragma unroll
                for (int i = 0; i < 4; i++)
                    mma16(c[i][j], a[i][0], a[i][1], a[i][2], a[i][3], b0, b1);
            }
        }
        __syncthreads();
    }

    // ---- epilogue ----
    #pragma unroll
    for (int i = 0; i < 4; i++) {
        const int gm0 = m0 + wm + i * 16 + r;     // rows for c0/c1; +8 for c2/c3
        if (mode == 0) {
            const int b = gm0 >> 11;
            const int t = gm0 & 2047;
            #pragma unroll
            for (int j = 0; j < 4; j++) {
                const int col = n0 + wn + j * 8 + qd * 2;
                const int mat = col >> 10;
                const int rem = col & 1023;
                const int h   = rem >> 6;
                const int d   = rem & 63;
                __half* base = (mat == 0) ? g_qh : (mat == 1 ? g_kh : g_vh);
                const float sc = (mat == 0) ? QSCALE : 1.0f;
                size_t o0 = ((size_t)((b * 16 + h) * 2048 + t)) * 64 + d;
                *(uint32_t*)(base + o0) =
                    f2h2(c[i][j][0] * sc, c[i][j][1] * sc);
                *(uint32_t*)(base + o0 + 8 * 64) =
                    f2h2(c[i][j][2] * sc, c[i][j][3] * sc);
            }
        } else {
            #pragma unroll
            for (int j = 0; j < 4; j++) {
                const int col = n0 + wn + j * 8 + qd * 2;
                float2 bv = *(const float2*)(bias + col);
                float* d0 = out + (size_t)gm0 * EE + col;
                *(float2*)d0            = make_float2(c[i][j][0] + bv.x, c[i][j][1] + bv.y);
                *(float2*)(d0 + 8 * EE) = make_float2(c[i][j][2] + bv.x, c[i][j][3] + bv.y);
            }
        }
    }
}

// ---------------------------------------------------------------------------
// Causal flash attention, fp16 mma.sync (FA2-style, register-resident P).
// 256 threads / 8 warps; q-tile 128 (16 rows per warp), k-tile 64.
// Q fragments loaded directly from gmem (pre-scaled). K fragments via LDS.32,
// V fragments via ldmatrix.x2.trans. P never touches SMEM: the S C-fragment
// repacks (half2) directly into the PV A-fragment.
// SMEM: K[2][64*72] + V[2][64*72] halves = 36864 B.
// ---------------------------------------------------------------------------
#define AM 128
#define SK 72
#define KVBUF (64 * SK)

__global__ __launch_bounds__(256, 2) void attn_kernel()
{
    extern __shared__ __half smk[];
    __half* K0 = smk;                  // [2][64][72]
    __half* V0 = smk + 2 * KVBUF;      // [2][64][72]

    const int bh = blockIdx.y;
    const int b  = bh >> 4;
    const int h  = bh & 15;
    const int q0 = TT - AM - blockIdx.x * AM;   // longest first

    const int tid  = threadIdx.x;
    const int lane = tid & 31;
    const int wid  = tid >> 5;
    const int wm   = wid * 16;
    const int r    = lane >> 2;
    const int qd   = lane & 3;

    const __half* qg = g_qh + ((size_t)bh * TT + q0) * HD;
    const __half* kg = g_kh + (size_t)bh * TT * HD;
    const __half* vg = g_vh + (size_t)bh * TT * HD;

    // ---- K/V tile prefetch: t -> buffer t&1 ----
    auto issueKV = [&](int t) {
        const int p  = t & 1;
        const int s0 = t * 64;
        #pragma unroll
        for (int rr = 0; rr < 2; rr++) {
            int it  = tid + 256 * rr;
            int row = it >> 3;
            int c8  = it & 7;
            uint32_t dk = smem_u32(K0 + p * KVBUF + row * SK + c8 * 8);
            CP16(dk, kg + (size_t)(s0 + row) * 64 + c8 * 8);
            uint32_t dv = smem_u32(V0 + p * KVBUF + row * SK + c8 * 8);
            CP16(dv, vg + (size_t)(s0 + row) * 64 + c8 * 8);
        }
        CP_COMMIT();
    };

    const int nt = q0 / 64 + 2;          // covers s0 <= q0 + 127
    issueKV(0);

    // ---- Q fragments straight from gmem (already scaled by QSCALE) ----
    uint32_t qa[4][4];
    {
        const __half* q0p = qg + (size_t)(wm + r) * 64 + 2 * qd;
        #pragma unroll
        for (int s = 0; s < 4; s++) {
            qa[s][0] = *(const uint32_t*)(q0p + s * 16);
            qa[s][1] = *(const uint32_t*)(q0p + 8 * 64 + s * 16);
            qa[s][2] = *(const uint32_t*)(q0p + s * 16 + 8);
            qa[s][3] = *(const uint32_t*)(q0p + 8 * 64 + s * 16 + 8);
        }
    }

    float o[8][4] = {};
    float m0r = -1e30f, m1r = -1e30f, l0 = 0.f, l1 = 0.f;

    for (int t = 0; t < nt; t++) {
        const int p  = t & 1;
        const int s0 = t * 64;
        if (t + 1 < nt) { issueKV(t + 1); CP_WAIT1(); }
        else            { CP_WAIT0(); }
        __syncthreads();

        if (s0 <= q0 + wm + 15) {       // warp not fully masked
            const __half* Ks = K0 + p * KVBUF;
            const __half* Vs = V0 + p * KVBUF;

            // ---- S = Q K^T (16 x 64 per warp), log2-scaled ----
            float c[8][4] = {};
            #pragma unroll
            for (int s = 0; s < 4; s++) {
                #pragma unroll
                for (int j = 0; j < 8; j++) {
                    const __half* krow = Ks + (j * 8 + r) * SK + s * 16 + 2 * qd;
                    uint32_t b0 = *(const uint32_t*)(krow);
                    uint32_t b1 = *(const uint32_t*)(krow + 8);
                    mma16(c[j], qa[s][0], qa[s][1], qa[s][2], qa[s][3], b0, b1);
                }
            }

            // ---- causal mask (diagonal region only) ----
            if (s0 + 63 > q0 + wm) {
                const int row0 = q0 + wm + r, row1 = row0 + 8;
                #pragma unroll
                for (int j = 0; j < 8; j++) {
                    const int cl = s0 + j * 8 + qd * 2;
                    if (cl     > row0) c[j][0] = -1e30f;
                    if (cl + 1 > row0) c[j][1] = -1e30f;
                    if (cl     > row1) c[j][2] = -1e30f;
                    if (cl + 1 > row1) c[j][3] = -1e30f;
                }
            }

            // ---- online softmax (base-2) ----
            float mx0 = -1e30f, mx1 = -1e30f;
            #pragma unroll
            for (int j = 0; j < 8; j++) {
                mx0 = fmaxf(mx0, fmaxf(c[j][0], c[j][1]));
                mx1 = fmaxf(mx1, fmaxf(c[j][2], c[j][3]));
            }
            mx0 = fmaxf(mx0, __shfl_xor_sync(0xffffffffu, mx0, 1));
            mx0 = fmaxf(mx0, __shfl_xor_sync(0xffffffffu, mx0, 2));
            mx1 = fmaxf(mx1, __shfl_xor_sync(0xffffffffu, mx1, 1));
            mx1 = fmaxf(mx1, __shfl_xor_sync(0xffffffffu, mx1, 2));

            const float nm0 = fmaxf(m0r, mx0), nm1 = fmaxf(m1r, mx1);
            const float f0 = exp2f(m0r - nm0), f1 = exp2f(m1r - nm1);
            float rs0 = 0.f, rs1 = 0.f;
            #pragma unroll
            for (int j = 0; j < 8; j++) {
                c[j][0] = exp2f(c[j][0] - nm0);
                c[j][1] = exp2f(c[j][1] - nm0);
                c[j][2] = exp2f(c[j][2] - nm1);
                c[j][3] = exp2f(c[j][3] - nm1);
                rs0 += c[j][0] + c[j][1];
                rs1 += c[j][2] + c[j][3];
            }
            rs0 += __shfl_xor_sync(0xffffffffu, rs0, 1);
            rs0 += __shfl_xor_sync(0xffffffffu, rs0, 2);
            rs1 += __shfl_xor_sync(0xffffffffu, rs1, 1);
            rs1 += __shfl_xor_sync(0xffffffffu, rs1, 2);

            l0 = l0 * f0 + rs0;  m0r = nm0;
            l1 = l1 * f1 + rs1;  m1r = nm1;
            #pragma unroll
            for (int j = 0; j < 8; j++) {
                o[j][0] *= f0;  o[j][1] *= f0;
                o[j][2] *= f1;  o[j][3] *= f1;
            }

            // ---- P: repack S C-fragments into PV A-fragments (registers) ----
            uint32_t ph[4][4];
            #pragma unroll
            for (int s = 0; s < 4; s++) {
                ph[s][0] = f2h2(c[2 * s][0],     c[2 * s][1]);       // (r,   k 2qd..)
                ph[s][1] = f2h2(c[2 * s][2],     c[2 * s][3]);       // (r+8, k 2qd..)
                ph[s][2] = f2h2(c[2 * s + 1][0], c[2 * s + 1][1]);   // (r,   k 8+2qd..)
                ph[s][3] = f2h2(c[2 * s + 1][2], c[2 * s + 1][3]);   // (r+8, k 8+2qd..)
            }

            // ---- O += P V : V fragments via ldmatrix.x2.trans ----
            #pragma unroll
            for (int s = 0; s < 4; s++) {
                #pragma unroll
                for (int j = 0; j < 8; j++) {
                    uint32_t vaddr = smem_u32(Vs + (s * 16 + (lane & 15)) * SK + j * 8);
                    uint32_t vb0, vb1;
                    asm volatile(
                        "ldmatrix.sync.aligned.m8n8.x2.trans.shared.b16 {%0,%1}, [%2];"
                        : "=r"(vb0), "=r"(vb1) : "r"(vaddr));
                    mma16(o[j], ph[s][0], ph[s][1], ph[s][2], ph[s][3], vb0, vb1);
                }
            }
        }
        __syncthreads();   // all warps done with buffer t&1 before reuse
    }

    // ---- epilogue: normalize, store half to g_atth[B,T,E] ----
    const float inv0 = 1.0f / l0, inv1 = 1.0f / l1;
    const int t0 = q0 + wm + r;
    __half* og0 = g_atth + ((size_t)b * TT + t0) * EE + h * 64;
    __half* og1 = og0 + 8 * EE;
    #pragma unroll
    for (int j = 0; j < 8; j++) {
        *(uint32_t*)(og0 + j * 8 + qd * 2) = f2h2(o[j][0] * inv0, o[j][1] * inv0);
        *(uint32_t*)(og1 + j * 8 + qd * 2) = f2h2(o[j][2] * inv1, o[j][3] * inv1);
    }
}

// ---------------------------------------------------------------------------
extern "C" void kernel_launch(void* const* d_in, const int* in_sizes, int n_in,
                              void* d_out, int out_size)
{
    const float* x  = (const float*)d_in[0];
    const float* Wq = (const float*)d_in[1];
    const float* Wk = (const float*)d_in[2];
    const float* Wv = (const float*)d_in[3];
    const float* Wo = (const float*)d_in[4];
    const float* bo = (const float*)d_in[5];
    float* out = (float*)d_out;

    __half *wt_ptr, *att_ptr, *xh_ptr, *wo_ptr;
    cudaGetSymbolAddress((void**)&wt_ptr,  g_wth);
    cudaGetSymbolAddress((void**)&att_ptr, g_atth);
    cudaGetSymbolAddress((void**)&xh_ptr,  g_xh);
    cudaGetSymbolAddress((void**)&wo_ptr,  g_woh);

    // 1) fp16-convert x and Wo; pack+convert per-head weights K-major
    {
        int n4x = BB * TT * EE / 4;
        to_half_kernel<<<(n4x + 255) / 256, 256>>>((const float4*)x, (uint2*)xh_ptr, n4x);
        int n4w = EE * EE / 4;
        to_half_kernel<<<(n4w + 255) / 256, 256>>>((const float4*)Wo, (uint2*)wo_ptr, n4w);
        dim3 grid(EE / 32, HH * 2, 3);
        dim3 blk(32, 8);
        wt_transpose_kernel<<<grid, blk>>>(Wq, Wk, Wv);
    }

    const int gemm_smem = 4 * ABUF * sizeof(__half);          // 73728 B
    cudaFuncSetAttribute(gemm_h_kernel,
                         cudaFuncAttributeMaxDynamicSharedMemorySize, gemm_smem);
    const int attn_smem = 4 * KVBUF * sizeof(__half);         // 36864 B
    cudaFuncSetAttribute(attn_kernel,
                         cudaFuncAttributeMaxDynamicSharedMemorySize, attn_smem);

    // 2) QKV: [8192,3072] = g_xh @ g_wth^T  (half scatter -> g_qh/g_kh/g_vh)
    {
        dim3 grid(3 * EE / 128, (BB * TT) / 128);   // (24, 64)
        gemm_h_kernel<<<grid, 256, gemm_smem>>>(0, xh_ptr, wt_ptr, nullptr, nullptr);
    }

    // 3) attention
    {
        dim3 gridB(TT / AM, BB * HH);               // (16, 64)
        attn_kernel<<<gridB, 256, attn_smem>>>();
    }

    // 4) O projection: out = g_atth @ g_woh^T + bo
    {
        dim3 grid(EE / 128, (BB * TT) / 128);       // (8, 64)
        gemm_h_kernel<<<grid, 256, gemm_smem>>>(1, att_ptr, wo_ptr, bo, out);
    }
}